// round 3
// baseline (speedup 1.0000x reference)
#include <cuda_runtime.h>

// Problem constants
#define B_SZ 16
#define NHEAD 8
#define DKDIM 64
#define NPIX 1024            // H*W
#define CCH 512
#define MTOT (B_SZ * NPIX)   // 16384

// Scratch (allocation-guard-safe __device__ globals)
// Layouts:
//   g_q/g_k/g_v : [o][m] with o = d*8 + h, m = b*1024 + n   (proj GEMM natural output)
//   g_ao        : [c][m] with c = h*64 + d                  (attention output, row-major for GEMM2)
__device__ float g_q[CCH * MTOT];
__device__ float g_k[CCH * MTOT];
__device__ float g_v[CCH * MTOT];
__device__ float g_ao[CCH * MTOT];

// ---------------------------------------------------------------------------
// GEMM: Y[o][m] = sum_c W[o][c] * X[c][m]  (+ bias[o])
// M = 512 (o), K = 512 (c), N = 16384 (m = b*1024 + n)
// x4d: X is x tensor [b][c][n] (addr = b*524288 + c*1024 + n), else row-major [c][m]
// y4d: Y is out tensor [b][o][n] (addr = b*524288 + o*1024 + n), else row-major [o][m]
// Block tile 128(o) x 128(m), K-chunk 16, 256 threads, 8x8 microtile.
// ---------------------------------------------------------------------------
__global__ __launch_bounds__(256) void gemm512(
    const float* __restrict__ W, const float* __restrict__ X,
    float* __restrict__ Y, const float* __restrict__ bias,
    int x4d, int y4d)
{
    __shared__ float Ws[16][132];   // [kc][oo], pad 132 keeps float4 alignment
    __shared__ float Xs[16][128];   // [kc][mm]

    const int m0 = blockIdx.x * 128;
    const int o0 = blockIdx.y * 128;
    const int tid = threadIdx.x;
    const int ty = tid >> 4, tx = tid & 15;
    const int b  = m0 >> 10;
    const int n0 = m0 & 1023;

    const float* Xb = x4d ? (X + b * CCH * NPIX + n0) : (X + m0);
    const int xstr = x4d ? NPIX : MTOT;

    float acc[8][8];
#pragma unroll
    for (int i = 0; i < 8; i++)
#pragma unroll
        for (int j = 0; j < 8; j++) acc[i][j] = 0.f;

    for (int c0 = 0; c0 < CCH; c0 += 16) {
        // load W tile (transposed into [kc][oo])
#pragma unroll
        for (int r = 0; r < 8; r++) {
            int idx = tid + r * 256;
            int oo = idx >> 4, kc = idx & 15;
            Ws[kc][oo] = W[(o0 + oo) * CCH + c0 + kc];
        }
        // load X tile via float4 (coalesced)
#pragma unroll
        for (int r = 0; r < 2; r++) {
            int idx4 = tid + r * 256;
            int kc = idx4 >> 5, mm = (idx4 & 31) * 4;
            *(float4*)(&Xs[kc][mm]) = *(const float4*)(Xb + (c0 + kc) * xstr + mm);
        }
        __syncthreads();
#pragma unroll
        for (int kc = 0; kc < 16; kc++) {
            float wf[8], xf[8];
            *(float4*)(wf)     = *(const float4*)(&Ws[kc][ty * 8]);
            *(float4*)(wf + 4) = *(const float4*)(&Ws[kc][ty * 8 + 4]);
            *(float4*)(xf)     = *(const float4*)(&Xs[kc][tx * 8]);
            *(float4*)(xf + 4) = *(const float4*)(&Xs[kc][tx * 8 + 4]);
#pragma unroll
            for (int i = 0; i < 8; i++)
#pragma unroll
                for (int j = 0; j < 8; j++)
                    acc[i][j] = fmaf(wf[i], xf[j], acc[i][j]);
        }
        __syncthreads();
    }

#pragma unroll
    for (int i = 0; i < 8; i++) {
        int o = o0 + ty * 8 + i;
        float bv = bias ? bias[o] : 0.f;
        float* yb = y4d ? (Y + b * CCH * NPIX + o * NPIX + n0 + tx * 8)
                        : (Y + o * MTOT + m0 + tx * 8);
        float4 v0 = make_float4(acc[i][0] + bv, acc[i][1] + bv, acc[i][2] + bv, acc[i][3] + bv);
        float4 v1 = make_float4(acc[i][4] + bv, acc[i][5] + bv, acc[i][6] + bv, acc[i][7] + bv);
        *(float4*)(yb)     = v0;
        *(float4*)(yb + 4) = v1;
    }
}

// ---------------------------------------------------------------------------
// Fused attention: per (b,h), flash-style online softmax.
// Thread = one query (256 queries per block, grid (4, B*NH)).
// q row + output accumulator in registers; K/V tiles broadcast from smem;
// content-aware 2D rel-pos bias computed per query into smem (transposed,
// conflict-free), added before softmax.
// ---------------------------------------------------------------------------
#define KT 16
#define REL_F (63 * 64)                       // 4032 floats per rel table
#define ATTN_SMEM_FLOATS (REL_F * 2 + 32 * 256 * 2 + KT * 68 * 2)

__global__ __launch_bounds__(256) void attn512(
    const float* __restrict__ rel_h, const float* __restrict__ rel_w)
{
    extern __shared__ float sm[];
    float* rh_s = sm;                       // [63][64]
    float* rw_s = rh_s + REL_F;             // [63][64]
    float* bh_s = rw_s + REL_F;             // [32][256] : bias over key-row i, per tid
    float* bw_s = bh_s + 32 * 256;          // [32][256] : bias over key-col j, per tid
    float* Ks   = bw_s + 32 * 256;          // [KT][68]  : key tile, d contiguous
    float* Vs   = Ks + KT * 68;             // [KT][68]

    const int tid = threadIdx.x;
    const int bh = blockIdx.y;
    const int b = bh >> 3, h = bh & 7;
    const int n = blockIdx.x * 256 + tid;   // query index
    const int qx = n >> 5, qy = n & 31;     // query pixel (row, col)

    // stage rel tables
    for (int i = tid; i < REL_F; i += 256) { rh_s[i] = rel_h[i]; rw_s[i] = rel_w[i]; }

    // q row -> registers. o = d*8 + h, addr = o*16384 + b*1024 + n
    float q[64];
    const float* qp = g_q + h * MTOT + b * NPIX + n;
#pragma unroll
    for (int d = 0; d < 64; d++) q[d] = qp[d * NHEAD * MTOT];
    __syncthreads();

    // bias vectors: bh[i] = q . rel_h[i - qx + 31], bw[j] = q . rel_w[j - qy + 31]
    // Loop over ALL 63 rows (warp-uniform address -> broadcast LDS), store the
    // 32 in-range results. Avoids 32-way bank conflicts from per-lane rows.
    for (int r = 0; r < 63; r++) {
        const float* rp = rh_s + r * 64;
        float s0 = 0, s1 = 0, s2 = 0, s3 = 0;
#pragma unroll
        for (int d = 0; d < 64; d += 4) {
            float4 rv = *(const float4*)(rp + d);
            s0 = fmaf(q[d], rv.x, s0);     s1 = fmaf(q[d + 1], rv.y, s1);
            s2 = fmaf(q[d + 2], rv.z, s2); s3 = fmaf(q[d + 3], rv.w, s3);
        }
        int i = r + qx - 31;
        if (i >= 0 && i < 32) bh_s[i * 256 + tid] = (s0 + s1) + (s2 + s3);
    }
    for (int r = 0; r < 63; r++) {
        const float* rp = rw_s + r * 64;
        float s0 = 0, s1 = 0, s2 = 0, s3 = 0;
#pragma unroll
        for (int d = 0; d < 64; d += 4) {
            float4 rv = *(const float4*)(rp + d);
            s0 = fmaf(q[d], rv.x, s0);     s1 = fmaf(q[d + 1], rv.y, s1);
            s2 = fmaf(q[d + 2], rv.z, s2); s3 = fmaf(q[d + 3], rv.w, s3);
        }
        int j = r + qy - 31;
        if (j >= 0 && j < 32) bw_s[j * 256 + tid] = (s0 + s1) + (s2 + s3);
    }

    // online-softmax main loop over 1024 keys
    float mrun = -1e30f, lrun = 0.f;
    float acc[64];
#pragma unroll
    for (int d = 0; d < 64; d++) acc[d] = 0.f;

    const float* Kb = g_k + h * MTOT + b * NPIX;
    const float* Vb = g_v + h * MTOT + b * NPIX;

    for (int k0 = 0; k0 < NPIX; k0 += KT) {
        __syncthreads();   // protect Ks/Vs from previous-iteration readers
#pragma unroll
        for (int r = 0; r < 4; r++) {
            int idx = tid + r * 256;           // KT*64 = 1024 elements
            int kk = idx & 15, d = idx >> 4;
            Ks[kk * 68 + d] = Kb[d * NHEAD * MTOT + k0 + kk];
            Vs[kk * 68 + d] = Vb[d * NHEAD * MTOT + k0 + kk];
        }
        __syncthreads();

        float s[KT];
#pragma unroll
        for (int kk = 0; kk < KT; kk++) {
            const float* kr = Ks + kk * 68;
            float s0 = 0, s1 = 0, s2 = 0, s3 = 0;
#pragma unroll
            for (int d = 0; d < 64; d += 4) {
                float4 kv = *(const float4*)(kr + d);   // broadcast across warp
                s0 = fmaf(q[d], kv.x, s0);     s1 = fmaf(q[d + 1], kv.y, s1);
                s2 = fmaf(q[d + 2], kv.z, s2); s3 = fmaf(q[d + 3], kv.w, s3);
            }
            int k = k0 + kk;
            float bias = bh_s[(k >> 5) * 256 + tid] + bw_s[(k & 31) * 256 + tid];
            s[kk] = ((s0 + s1) + (s2 + s3) + bias) * 0.125f;   // /sqrt(64)
        }

        float tmax = s[0];
#pragma unroll
        for (int kk = 1; kk < KT; kk++) tmax = fmaxf(tmax, s[kk]);
        float mnew = fmaxf(mrun, tmax);
        float corr = __expf(mrun - mnew);
        lrun *= corr;
#pragma unroll
        for (int kk = 0; kk < KT; kk++) { s[kk] = __expf(s[kk] - mnew); lrun += s[kk]; }
        mrun = mnew;

#pragma unroll
        for (int d = 0; d < 64; d += 4) {
            float a0 = acc[d] * corr, a1 = acc[d + 1] * corr;
            float a2 = acc[d + 2] * corr, a3 = acc[d + 3] * corr;
#pragma unroll
            for (int kk = 0; kk < KT; kk++) {
                float4 vv = *(const float4*)(Vs + kk * 68 + d);  // broadcast
                a0 = fmaf(s[kk], vv.x, a0); a1 = fmaf(s[kk], vv.y, a1);
                a2 = fmaf(s[kk], vv.z, a2); a3 = fmaf(s[kk], vv.w, a3);
            }
            acc[d] = a0; acc[d + 1] = a1; acc[d + 2] = a2; acc[d + 3] = a3;
        }
    }

    // write attention output: c = h*64 + d, addr = c*16384 + b*1024 + n
    float inv = 1.f / lrun;
    float* ob = g_ao + (h * DKDIM) * MTOT + b * NPIX + n;
#pragma unroll
    for (int d = 0; d < 64; d++) ob[d * MTOT] = acc[d] * inv;
}

// ---------------------------------------------------------------------------
extern "C" void kernel_launch(void* const* d_in, const int* in_sizes, int n_in,
                              void* d_out, int out_size)
{
    const float* x     = (const float*)d_in[0];
    const float* w_q   = (const float*)d_in[1];
    const float* w_k   = (const float*)d_in[2];
    const float* w_v   = (const float*)d_in[3];
    const float* w_o   = (const float*)d_in[4];
    const float* b_o   = (const float*)d_in[5];
    const float* rel_h = (const float*)d_in[6];
    const float* rel_w = (const float*)d_in[7];
    float* out = (float*)d_out;

    float *pq, *pk, *pv, *pa;
    cudaGetSymbolAddress((void**)&pq, g_q);
    cudaGetSymbolAddress((void**)&pk, g_k);
    cudaGetSymbolAddress((void**)&pv, g_v);
    cudaGetSymbolAddress((void**)&pa, g_ao);

    dim3 gg(128, 4);   // 128 m-tiles, 4 o-tiles
    // q/k/v projections: read x as 4D, write row-major scratch
    gemm512<<<gg, 256>>>(w_q, x, pq, nullptr, 1, 0);
    gemm512<<<gg, 256>>>(w_k, x, pk, nullptr, 1, 0);
    gemm512<<<gg, 256>>>(w_v, x, pv, nullptr, 1, 0);

    // fused attention
    int smem = ATTN_SMEM_FLOATS * (int)sizeof(float);   // ~106 KB
    cudaFuncSetAttribute(attn512, cudaFuncAttributeMaxDynamicSharedMemorySize, smem);
    attn512<<<dim3(4, B_SZ * NHEAD), 256, smem>>>(rel_h, rel_w);

    // output projection: row-major scratch in, 4D output, + b_o
    gemm512<<<gg, 256>>>(w_o, pa, out, b_o, 0, 1);
}

// round 8
// speedup vs baseline: 1.3204x; 1.3204x over previous
#include <cuda_runtime.h>
#include <cstdint>

// Problem constants
#define B_SZ 16
#define NHEAD 8
#define DKDIM 64
#define NPIX 1024            // H*W
#define CCH 512
#define MTOT (B_SZ * NPIX)   // 16384

// Scratch (allocation-guard-safe __device__ globals)
__device__ float g_q[CCH * MTOT];
__device__ float g_k[CCH * MTOT];
__device__ float g_v[CCH * MTOT];
__device__ float g_ao[CCH * MTOT];

__device__ __forceinline__ uint32_t f2tf32(float f) {
    uint32_t r; asm("cvt.rna.tf32.f32 %0, %1;" : "=r"(r) : "f"(f)); return r;
}

// warp-level tf32 MMA, m16n8k8, fp32 accumulate (base sm_80+ feature — no 'a' gate)
__device__ __forceinline__ void mma_tf32(float* d, const uint32_t* a, const uint32_t* b) {
    asm volatile(
        "mma.sync.aligned.m16n8k8.row.col.f32.tf32.tf32.f32 "
        "{%0,%1,%2,%3}, {%4,%5,%6,%7}, {%8,%9}, {%0,%1,%2,%3};"
        : "+f"(d[0]), "+f"(d[1]), "+f"(d[2]), "+f"(d[3])
        : "r"(a[0]), "r"(a[1]), "r"(a[2]), "r"(a[3]), "r"(b[0]), "r"(b[1]));
}

// ---------------------------------------------------------------------------
// Tensor-core GEMM (mma.sync tf32): Y[o][m] = sum_c W[o][c] * X[c][m] (+bias)
// M=512 (o), K=512 (c), N=16384 (m = b*1024 + n)
// x4d: X is x tensor [b][c][n]; y4d: Y is out tensor [b][o][n].
// CTA tile 128x128, K-chunk 32, 8 warps (2 o x 4 m), warp tile 64x32.
// ---------------------------------------------------------------------------
__global__ __launch_bounds__(256) void gemm_mma(
    const float* __restrict__ W, const float* __restrict__ X,
    float* __restrict__ Y, const float* __restrict__ bias,
    int x4d, int y4d)
{
    __shared__ float As[128][36];   // [o][c] tf32 bits; stride 36 -> conflict-free frags
    __shared__ float Bs[32][136];   // [c][m] tf32 bits; stride 136 -> conflict-free frags

    const int tid = threadIdx.x, wid = tid >> 5, lane = tid & 31;
    const int gid = lane >> 2, tig = lane & 3;
    const int m0 = blockIdx.x * 128;   // N dim (m)
    const int o0 = blockIdx.y * 128;   // M dim (o)
    const int b  = m0 >> 10, n0 = m0 & 1023;
    const int wo = (wid >> 2) * 64;    // warp o-offset in tile
    const int wm = (wid & 3) * 32;     // warp m-offset in tile

    const float* Xb = x4d ? (X + (size_t)b * CCH * NPIX + n0) : (X + m0);
    const int xstr = x4d ? NPIX : MTOT;

    float acc[4][4][4];
#pragma unroll
    for (int mt = 0; mt < 4; mt++)
#pragma unroll
        for (int nt = 0; nt < 4; nt++)
#pragma unroll
            for (int i = 0; i < 4; i++) acc[mt][nt][i] = 0.f;

    for (int c0 = 0; c0 < CCH; c0 += 32) {
        // A tile: W[o0+oo][c0+kc], 128x32, float4 along c, tf32-rounded
#pragma unroll
        for (int j = 0; j < 4; j++) {
            int idx4 = tid + j * 256;
            int oo = idx4 >> 3, kc4 = (idx4 & 7) * 4;
            float4 v = *(const float4*)(W + (size_t)(o0 + oo) * CCH + c0 + kc4);
            uint4 t = make_uint4(f2tf32(v.x), f2tf32(v.y), f2tf32(v.z), f2tf32(v.w));
            *(uint4*)(&As[oo][kc4]) = t;
        }
        // B tile: X[c0+kc][m0+mm], 32x128, float4 along m (coalesced), tf32-rounded
#pragma unroll
        for (int j = 0; j < 4; j++) {
            int idx4 = tid + j * 256;
            int kc = idx4 >> 5, mm4 = (idx4 & 31) * 4;
            float4 v = *(const float4*)(Xb + (size_t)(c0 + kc) * xstr + mm4);
            uint4 t = make_uint4(f2tf32(v.x), f2tf32(v.y), f2tf32(v.z), f2tf32(v.w));
            *(uint4*)(&Bs[kc][mm4]) = t;
        }
        __syncthreads();

#pragma unroll
        for (int ks = 0; ks < 4; ks++) {
            const int c8 = ks * 8;
            uint32_t a[4][4], bb[4][2];
#pragma unroll
            for (int mt = 0; mt < 4; mt++) {
                int r = wo + mt * 16 + gid;
                a[mt][0] = __float_as_uint(As[r][c8 + tig]);
                a[mt][1] = __float_as_uint(As[r + 8][c8 + tig]);
                a[mt][2] = __float_as_uint(As[r][c8 + tig + 4]);
                a[mt][3] = __float_as_uint(As[r + 8][c8 + tig + 4]);
            }
#pragma unroll
            for (int nt = 0; nt < 4; nt++) {
                int cc = wm + nt * 8 + gid;
                bb[nt][0] = __float_as_uint(Bs[c8 + tig][cc]);
                bb[nt][1] = __float_as_uint(Bs[c8 + tig + 4][cc]);
            }
#pragma unroll
            for (int mt = 0; mt < 4; mt++)
#pragma unroll
                for (int nt = 0; nt < 4; nt++)
                    mma_tf32(acc[mt][nt], a[mt], bb[nt]);
        }
        __syncthreads();
    }

    // Epilogue: c0/c1 at (row=gid, col=tig*2, tig*2+1), c2/c3 at row+8
    const int ystr = y4d ? NPIX : MTOT;
#pragma unroll
    for (int mt = 0; mt < 4; mt++) {
        int o = o0 + wo + mt * 16 + gid;
        float bv0 = bias ? bias[o] : 0.f;
        float bv1 = bias ? bias[o + 8] : 0.f;
        float* y0 = y4d ? (Y + (size_t)b * CCH * NPIX + (size_t)o * NPIX + n0)
                        : (Y + (size_t)o * MTOT + m0);
        float* y1 = y0 + 8 * (size_t)ystr;
#pragma unroll
        for (int nt = 0; nt < 4; nt++) {
            int m = wm + nt * 8 + tig * 2;
            *(float2*)(y0 + m) = make_float2(acc[mt][nt][0] + bv0, acc[mt][nt][1] + bv0);
            *(float2*)(y1 + m) = make_float2(acc[mt][nt][2] + bv1, acc[mt][nt][3] + bv1);
        }
    }
}

// ---------------------------------------------------------------------------
// Fused attention (unchanged): per (b,h) flash-style online softmax.
// ---------------------------------------------------------------------------
#define KT 16
#define REL_F (63 * 64)
#define ATTN_SMEM_FLOATS (REL_F * 2 + 32 * 256 * 2 + KT * 68 * 2)

__global__ __launch_bounds__(256) void attn512(
    const float* __restrict__ rel_h, const float* __restrict__ rel_w)
{
    extern __shared__ float smf[];
    float* rh_s = smf;
    float* rw_s = rh_s + REL_F;
    float* bh_s = rw_s + REL_F;             // [32][256]
    float* bw_s = bh_s + 32 * 256;          // [32][256]
    float* Ks   = bw_s + 32 * 256;          // [KT][68]
    float* Vs   = Ks + KT * 68;

    const int tid = threadIdx.x;
    const int bh = blockIdx.y;
    const int b = bh >> 3, h = bh & 7;
    const int n = blockIdx.x * 256 + tid;
    const int qx = n >> 5, qy = n & 31;

    for (int i = tid; i < REL_F; i += 256) { rh_s[i] = rel_h[i]; rw_s[i] = rel_w[i]; }

    float q[64];
    const float* qp = g_q + h * MTOT + b * NPIX + n;
#pragma unroll
    for (int d = 0; d < 64; d++) q[d] = qp[d * NHEAD * MTOT];
    __syncthreads();

    for (int r = 0; r < 63; r++) {
        const float* rp = rh_s + r * 64;
        float s0 = 0, s1 = 0, s2 = 0, s3 = 0;
#pragma unroll
        for (int d = 0; d < 64; d += 4) {
            float4 rv = *(const float4*)(rp + d);
            s0 = fmaf(q[d], rv.x, s0);     s1 = fmaf(q[d + 1], rv.y, s1);
            s2 = fmaf(q[d + 2], rv.z, s2); s3 = fmaf(q[d + 3], rv.w, s3);
        }
        int i = r + qx - 31;
        if (i >= 0 && i < 32) bh_s[i * 256 + tid] = (s0 + s1) + (s2 + s3);
    }
    for (int r = 0; r < 63; r++) {
        const float* rp = rw_s + r * 64;
        float s0 = 0, s1 = 0, s2 = 0, s3 = 0;
#pragma unroll
        for (int d = 0; d < 64; d += 4) {
            float4 rv = *(const float4*)(rp + d);
            s0 = fmaf(q[d], rv.x, s0);     s1 = fmaf(q[d + 1], rv.y, s1);
            s2 = fmaf(q[d + 2], rv.z, s2); s3 = fmaf(q[d + 3], rv.w, s3);
        }
        int j = r + qy - 31;
        if (j >= 0 && j < 32) bw_s[j * 256 + tid] = (s0 + s1) + (s2 + s3);
    }

    float mrun = -1e30f, lrun = 0.f;
    float acc[64];
#pragma unroll
    for (int d = 0; d < 64; d++) acc[d] = 0.f;

    const float* Kb = g_k + h * MTOT + b * NPIX;
    const float* Vb = g_v + h * MTOT + b * NPIX;

    for (int k0 = 0; k0 < NPIX; k0 += KT) {
        __syncthreads();
#pragma unroll
        for (int r = 0; r < 4; r++) {
            int idx = tid + r * 256;
            int kk = idx & 15, d = idx >> 4;
            Ks[kk * 68 + d] = Kb[d * NHEAD * MTOT + k0 + kk];
            Vs[kk * 68 + d] = Vb[d * NHEAD * MTOT + k0 + kk];
        }
        __syncthreads();

        float s[KT];
#pragma unroll
        for (int kk = 0; kk < KT; kk++) {
            const float* kr = Ks + kk * 68;
            float s0 = 0, s1 = 0, s2 = 0, s3 = 0;
#pragma unroll
            for (int d = 0; d < 64; d += 4) {
                float4 kv = *(const float4*)(kr + d);
                s0 = fmaf(q[d], kv.x, s0);     s1 = fmaf(q[d + 1], kv.y, s1);
                s2 = fmaf(q[d + 2], kv.z, s2); s3 = fmaf(q[d + 3], kv.w, s3);
            }
            int k = k0 + kk;
            float bias = bh_s[(k >> 5) * 256 + tid] + bw_s[(k & 31) * 256 + tid];
            s[kk] = ((s0 + s1) + (s2 + s3) + bias) * 0.125f;
        }

        float tmax = s[0];
#pragma unroll
        for (int kk = 1; kk < KT; kk++) tmax = fmaxf(tmax, s[kk]);
        float mnew = fmaxf(mrun, tmax);
        float corr = __expf(mrun - mnew);
        lrun *= corr;
#pragma unroll
        for (int kk = 0; kk < KT; kk++) { s[kk] = __expf(s[kk] - mnew); lrun += s[kk]; }
        mrun = mnew;

#pragma unroll
        for (int d = 0; d < 64; d += 4) {
            float a0 = acc[d] * corr, a1 = acc[d + 1] * corr;
            float a2 = acc[d + 2] * corr, a3 = acc[d + 3] * corr;
#pragma unroll
            for (int kk = 0; kk < KT; kk++) {
                float4 vv = *(const float4*)(Vs + kk * 68 + d);
                a0 = fmaf(s[kk], vv.x, a0); a1 = fmaf(s[kk], vv.y, a1);
                a2 = fmaf(s[kk], vv.z, a2); a3 = fmaf(s[kk], vv.w, a3);
            }
            acc[d] = a0; acc[d + 1] = a1; acc[d + 2] = a2; acc[d + 3] = a3;
        }
    }

    float inv = 1.f / lrun;
    float* ob = g_ao + (h * DKDIM) * MTOT + b * NPIX + n;
#pragma unroll
    for (int d = 0; d < 64; d++) ob[d * MTOT] = acc[d] * inv;
}

// ---------------------------------------------------------------------------
extern "C" void kernel_launch(void* const* d_in, const int* in_sizes, int n_in,
                              void* d_out, int out_size)
{
    const float* x     = (const float*)d_in[0];
    const float* w_q   = (const float*)d_in[1];
    const float* w_k   = (const float*)d_in[2];
    const float* w_v   = (const float*)d_in[3];
    const float* w_o   = (const float*)d_in[4];
    const float* b_o   = (const float*)d_in[5];
    const float* rel_h = (const float*)d_in[6];
    const float* rel_w = (const float*)d_in[7];
    float* out = (float*)d_out;

    float *pq, *pk, *pv, *pa;
    cudaGetSymbolAddress((void**)&pq, g_q);
    cudaGetSymbolAddress((void**)&pk, g_k);
    cudaGetSymbolAddress((void**)&pv, g_v);
    cudaGetSymbolAddress((void**)&pa, g_ao);

    dim3 gg(128, 4);   // 128 m-tiles, 4 o-tiles
    gemm_mma<<<gg, 256>>>(w_q, x, pq, nullptr, 1, 0);
    gemm_mma<<<gg, 256>>>(w_k, x, pk, nullptr, 1, 0);
    gemm_mma<<<gg, 256>>>(w_v, x, pv, nullptr, 1, 0);

    int smem = ATTN_SMEM_FLOATS * (int)sizeof(float);
    cudaFuncSetAttribute(attn512, cudaFuncAttributeMaxDynamicSharedMemorySize, smem);
    attn512<<<dim3(4, B_SZ * NHEAD), 256, smem>>>(rel_h, rel_w);

    gemm_mma<<<gg, 256>>>(w_o, pa, out, b_o, 0, 1);
}